// round 1
// baseline (speedup 1.0000x reference)
#include <cuda_runtime.h>

#define Bq 8
#define Hh 256
#define Ww 256
#define CINc 64
#define COUTc 64
#define STYLE_INc 512
#define CC 8          // cin chunk
#define TILE 16       // output tile edge

// scratch (no allocs allowed)
__device__ float g_s[Bq * CINc];
__device__ __align__(16) float g_wmod[Bq * CINc * 9 * COUTc];   // [b][ci][tap][co]

// ---------------------------------------------------------------------------
// Kernel 1: style modulation  s[b][ci] = style[b] . (mod_weight * 1/sqrt(512)) + bias[ci]
// ---------------------------------------------------------------------------
__global__ void k_style(const float* __restrict__ style,
                        const float* __restrict__ mw,
                        const float* __restrict__ mb) {
    int tid = threadIdx.x;           // 512 threads: b = tid>>6, ci = tid&63
    int b = tid >> 6;
    int ci = tid & 63;
    const float scale = 0.04419417382415922f;   // 1/sqrt(512)
    const float* st = style + b * STYLE_INc;
    float acc = 0.f;
    for (int k = 0; k < STYLE_INc; ++k)
        acc += st[k] * mw[k * CINc + ci];
    g_s[tid] = acc * scale + mb[ci];
}

// ---------------------------------------------------------------------------
// Kernel 2: modulate + demodulate conv weight, relayout to [b][ci][tap][co]
// grid (COUT, B), 64 threads (ci)
// ---------------------------------------------------------------------------
__global__ void k_modw(const float* __restrict__ weight) {
    int co = blockIdx.x;
    int b  = blockIdx.y;
    int ci = threadIdx.x;            // 64
    const float cscale = 1.0f / 24.0f;   // 1/sqrt(64*9)
    float sv = g_s[b * CINc + ci];
    const float* wp = weight + (co * CINc + ci) * 9;
    float v[9];
    float ssum = 0.f;
#pragma unroll
    for (int k = 0; k < 9; ++k) {
        v[k] = cscale * wp[k] * sv;
        ssum += v[k] * v[k];
    }
#pragma unroll
    for (int off = 16; off > 0; off >>= 1)
        ssum += __shfl_xor_sync(0xffffffffu, ssum, off);
    __shared__ float red[2];
    if ((ci & 31) == 0) red[ci >> 5] = ssum;
    __syncthreads();
    float demod = rsqrtf(red[0] + red[1] + 1e-8f);
#pragma unroll
    for (int k = 0; k < 9; ++k)
        g_wmod[((b * CINc + ci) * 9 + k) * COUTc + co] = v[k] * demod;
}

// ---------------------------------------------------------------------------
// Kernel 3: per-sample 3x3 SAME conv, NHWC fp32.
// Block = 256 threads -> 16x16 pixel tile, all 64 couts.
// Thread: 2x2 pixel micro-tile x 16 couts = 64 accumulators.
// ---------------------------------------------------------------------------
__global__ __launch_bounds__(256, 2)
void k_conv(const float* __restrict__ in, float* __restrict__ out) {
    __shared__ float sIn[CC * 18 * 19];                 // [ci][y][x], pitch 19
    __shared__ __align__(16) float sW[CC * 9 * COUTc];  // [ci*9+tap][co]

    const int b   = blockIdx.z;
    const int by0 = blockIdx.y * TILE;
    const int bx0 = blockIdx.x * TILE;
    const int tid = threadIdx.x;
    const int g   = tid & 3;        // cout group (16 couts)
    const int p   = tid >> 2;       // pixel group (2x2 micro-tile)
    const int py  = (p >> 3) << 1;
    const int px  = (p & 7) << 1;

    float acc[4][16];
#pragma unroll
    for (int d = 0; d < 4; ++d)
#pragma unroll
        for (int j = 0; j < 16; ++j) acc[d][j] = 0.f;

    const float* inb = in + (size_t)b * Hh * Ww * CINc;

    for (int cb = 0; cb < CINc; cb += CC) {
        __syncthreads();
        // stage input halo tile [CC][18][18] -> sIn[ci][y][x]
        for (int idx = tid; idx < CC * 18 * 18; idx += 256) {
            int ci  = idx & (CC - 1);
            int pos = idx >> 3;
            int y   = pos / 18;
            int x   = pos - y * 18;
            int gy  = by0 + y - 1;
            int gx  = bx0 + x - 1;
            float val = 0.f;
            if ((unsigned)gy < (unsigned)Hh && (unsigned)gx < (unsigned)Ww)
                val = inb[(gy * Ww + gx) * CINc + cb + ci];
            sIn[(ci * 18 + y) * 19 + x] = val;
        }
        // stage weight chunk [CC*9][64]
        {
            const float4* wsrc = (const float4*)(g_wmod + (size_t)((b * CINc + cb) * 9) * COUTc);
            float4* wdst = (float4*)sW;
            for (int idx = tid; idx < (CC * 9 * COUTc) / 4; idx += 256)
                wdst[idx] = wsrc[idx];
        }
        __syncthreads();

#pragma unroll
        for (int ci = 0; ci < CC; ++ci) {
            const float* ip = sIn + ci * 18 * 19;
#pragma unroll
            for (int ky = 0; ky < 3; ++ky) {
#pragma unroll
                for (int kx = 0; kx < 3; ++kx) {
                    const float i00 = ip[(py + ky) * 19 + px + kx];
                    const float i01 = ip[(py + ky) * 19 + px + kx + 1];
                    const float i10 = ip[(py + 1 + ky) * 19 + px + kx];
                    const float i11 = ip[(py + 1 + ky) * 19 + px + kx + 1];
                    const float4* wr =
                        (const float4*)(sW + ((ci * 3 + ky) * 3 + kx) * COUTc + g * 16);
#pragma unroll
                    for (int j = 0; j < 4; ++j) {
                        const float4 w = wr[j];
                        acc[0][4 * j + 0] += i00 * w.x;
                        acc[0][4 * j + 1] += i00 * w.y;
                        acc[0][4 * j + 2] += i00 * w.z;
                        acc[0][4 * j + 3] += i00 * w.w;
                        acc[1][4 * j + 0] += i01 * w.x;
                        acc[1][4 * j + 1] += i01 * w.y;
                        acc[1][4 * j + 2] += i01 * w.z;
                        acc[1][4 * j + 3] += i01 * w.w;
                        acc[2][4 * j + 0] += i10 * w.x;
                        acc[2][4 * j + 1] += i10 * w.y;
                        acc[2][4 * j + 2] += i10 * w.z;
                        acc[2][4 * j + 3] += i10 * w.w;
                        acc[3][4 * j + 0] += i11 * w.x;
                        acc[3][4 * j + 1] += i11 * w.y;
                        acc[3][4 * j + 2] += i11 * w.z;
                        acc[3][4 * j + 3] += i11 * w.w;
                    }
                }
            }
        }
    }

    // write back: 4 pixels x 16 couts (4x float4 each)
#pragma unroll
    for (int d = 0; d < 4; ++d) {
        const int gy = by0 + py + (d >> 1);
        const int gx = bx0 + px + (d & 1);
        float* op = out + (((size_t)b * Hh + gy) * Ww + gx) * COUTc + g * 16;
#pragma unroll
        for (int j = 0; j < 4; ++j) {
            float4 v = make_float4(acc[d][4 * j + 0], acc[d][4 * j + 1],
                                   acc[d][4 * j + 2], acc[d][4 * j + 3]);
            *(float4*)(op + 4 * j) = v;
        }
    }
}

// ---------------------------------------------------------------------------
extern "C" void kernel_launch(void* const* d_in, const int* in_sizes, int n_in,
                              void* d_out, int out_size) {
    const float* inputs     = (const float*)d_in[0];   // [8,256,256,64]
    const float* style      = (const float*)d_in[1];   // [8,512]
    const float* mod_weight = (const float*)d_in[2];   // [512,64]
    const float* mod_bias   = (const float*)d_in[3];   // [64]
    const float* weight     = (const float*)d_in[4];   // [1,64,64,3,3]
    float* out = (float*)d_out;

    k_style<<<1, 512>>>(style, mod_weight, mod_bias);
    k_modw<<<dim3(COUTc, Bq), 64>>>(weight);
    k_conv<<<dim3(Ww / TILE, Hh / TILE, Bq), 256>>>(inputs, out);
}

// round 2
// speedup vs baseline: 1.0213x; 1.0213x over previous
#include <cuda_runtime.h>

#define Bq 8
#define Hh 256
#define Ww 256
#define CINc 64
#define COUTc 64
#define STYLE_INc 512
#define CC 8          // cin chunk
#define TILE 16       // output tile edge

// scratch (no allocs allowed)
__device__ float g_s[Bq * CINc];
__device__ __align__(16) float g_wmod[Bq * CINc * 9 * COUTc];   // [b][ci][tap][co]

// packed fp32x2 helpers (sm_103a FFMA2 path — only reachable via PTX)
__device__ __forceinline__ unsigned long long bc2(float x) {
    unsigned long long r;
    asm("mov.b64 %0, {%1, %1};" : "=l"(r) : "f"(x));
    return r;
}
__device__ __forceinline__ float2 unp2(unsigned long long v) {
    float2 r;
    asm("mov.b64 {%0, %1}, %2;" : "=f"(r.x), "=f"(r.y) : "l"(v));
    return r;
}
#define FMA2(d, a, b) \
    asm("fma.rn.f32x2 %0, %1, %2, %0;" : "+l"(d) : "l"(a), "l"(b))

// ---------------------------------------------------------------------------
// Kernel 1: style modulation, split-K over 8 partials per batch row.
// grid = 8 (one per b), 512 threads: ci = tid&63, kpart = tid>>6
// ---------------------------------------------------------------------------
__global__ void k_style(const float* __restrict__ style,
                        const float* __restrict__ mw,
                        const float* __restrict__ mb) {
    const int b  = blockIdx.x;
    const int ci = threadIdx.x & 63;
    const int kp = threadIdx.x >> 6;         // 0..7
    const float scale = 0.04419417382415922f;   // 1/sqrt(512)
    const float* st = style + b * STYLE_INc;
    float acc = 0.f;
    const int k0 = kp * 64;
#pragma unroll 8
    for (int k = k0; k < k0 + 64; ++k)
        acc += st[k] * mw[k * CINc + ci];
    __shared__ float red[512];
    red[threadIdx.x] = acc;
    __syncthreads();
    if (kp == 0) {
        float s = 0.f;
#pragma unroll
        for (int j = 0; j < 8; ++j) s += red[j * 64 + ci];
        g_s[b * CINc + ci] = s * scale + mb[ci];
    }
}

// ---------------------------------------------------------------------------
// Kernel 2: modulate + demodulate conv weight, relayout to [b][ci][tap][co]
// grid (COUT, B), 64 threads (ci)
// ---------------------------------------------------------------------------
__global__ void k_modw(const float* __restrict__ weight) {
    int co = blockIdx.x;
    int b  = blockIdx.y;
    int ci = threadIdx.x;            // 64
    const float cscale = 1.0f / 24.0f;   // 1/sqrt(64*9)
    float sv = g_s[b * CINc + ci];
    const float* wp = weight + (co * CINc + ci) * 9;
    float v[9];
    float ssum = 0.f;
#pragma unroll
    for (int k = 0; k < 9; ++k) {
        v[k] = cscale * wp[k] * sv;
        ssum += v[k] * v[k];
    }
#pragma unroll
    for (int off = 16; off > 0; off >>= 1)
        ssum += __shfl_xor_sync(0xffffffffu, ssum, off);
    __shared__ float red[2];
    if ((ci & 31) == 0) red[ci >> 5] = ssum;
    __syncthreads();
    float demod = rsqrtf(red[0] + red[1] + 1e-8f);
#pragma unroll
    for (int k = 0; k < 9; ++k)
        g_wmod[((b * CINc + ci) * 9 + k) * COUTc + co] = v[k] * demod;
}

// ---------------------------------------------------------------------------
// Kernel 3: per-sample 3x3 SAME conv, NHWC fp32, packed f32x2 math.
// Block = 256 threads -> 16x16 pixel tile, all 64 couts.
// Thread: 2x2 pixel micro-tile x 16 couts = 32 packed (cout-pair) accumulators.
// ---------------------------------------------------------------------------
__global__ __launch_bounds__(256, 2)
void k_conv(const float* __restrict__ in, float* __restrict__ out) {
    __shared__ float sIn[CC * 18 * 19];                 // [ci][y][x], pitch 19
    __shared__ __align__(16) float sW[CC * 9 * COUTc];  // [ci*9+tap][co]

    const int b   = blockIdx.z;
    const int by0 = blockIdx.y * TILE;
    const int bx0 = blockIdx.x * TILE;
    const int tid = threadIdx.x;
    const int g   = tid & 3;        // cout group (16 couts)
    const int p   = tid >> 2;       // pixel group (2x2 micro-tile)
    const int py  = (p >> 3) << 1;
    const int px  = (p & 7) << 1;

    // acc2[d][j]: pixel d (2x2), cout pair j (couts g*16 + 2j, +2j+1)
    unsigned long long acc2[4][8];
#pragma unroll
    for (int d = 0; d < 4; ++d)
#pragma unroll
        for (int j = 0; j < 8; ++j) acc2[d][j] = 0ull;

    const float* inb = in + (size_t)b * Hh * Ww * CINc;

    for (int cb = 0; cb < CINc; cb += CC) {
        __syncthreads();
        // stage input halo tile [CC][18][18] -> sIn[ci][y][x]
        for (int idx = tid; idx < CC * 18 * 18; idx += 256) {
            int ci  = idx & (CC - 1);
            int pos = idx >> 3;
            int y   = pos / 18;
            int x   = pos - y * 18;
            int gy  = by0 + y - 1;
            int gx  = bx0 + x - 1;
            float val = 0.f;
            if ((unsigned)gy < (unsigned)Hh && (unsigned)gx < (unsigned)Ww)
                val = inb[(gy * Ww + gx) * CINc + cb + ci];
            sIn[(ci * 18 + y) * 19 + x] = val;
        }
        // stage weight chunk [CC*9][64]
        {
            const float4* wsrc = (const float4*)(g_wmod + (size_t)((b * CINc + cb) * 9) * COUTc);
            float4* wdst = (float4*)sW;
            for (int idx = tid; idx < (CC * 9 * COUTc) / 4; idx += 256)
                wdst[idx] = wsrc[idx];
        }
        __syncthreads();

#pragma unroll
        for (int ci = 0; ci < CC; ++ci) {
            const float* ip = sIn + ci * 18 * 19;
            // hoist 4x4 input patch, broadcast-packed
            unsigned long long xin[4][4];
#pragma unroll
            for (int r = 0; r < 4; ++r)
#pragma unroll
                for (int c = 0; c < 4; ++c)
                    xin[r][c] = bc2(ip[(py + r) * 19 + px + c]);
#pragma unroll
            for (int ky = 0; ky < 3; ++ky) {
#pragma unroll
                for (int kx = 0; kx < 3; ++kx) {
                    const ulonglong2* wr =
                        (const ulonglong2*)(sW + ((ci * 3 + ky) * 3 + kx) * COUTc + g * 16);
#pragma unroll
                    for (int j = 0; j < 4; ++j) {
                        const ulonglong2 w = wr[j];
                        FMA2(acc2[0][2 * j],     xin[ky][kx],         w.x);
                        FMA2(acc2[0][2 * j + 1], xin[ky][kx],         w.y);
                        FMA2(acc2[1][2 * j],     xin[ky][kx + 1],     w.x);
                        FMA2(acc2[1][2 * j + 1], xin[ky][kx + 1],     w.y);
                        FMA2(acc2[2][2 * j],     xin[ky + 1][kx],     w.x);
                        FMA2(acc2[2][2 * j + 1], xin[ky + 1][kx],     w.y);
                        FMA2(acc2[3][2 * j],     xin[ky + 1][kx + 1], w.x);
                        FMA2(acc2[3][2 * j + 1], xin[ky + 1][kx + 1], w.y);
                    }
                }
            }
        }
    }

    // write back: 4 pixels x 16 couts
#pragma unroll
    for (int d = 0; d < 4; ++d) {
        const int gy = by0 + py + (d >> 1);
        const int gx = bx0 + px + (d & 1);
        float* op = out + (((size_t)b * Hh + gy) * Ww + gx) * COUTc + g * 16;
#pragma unroll
        for (int j = 0; j < 4; ++j) {
            float2 lo = unp2(acc2[d][2 * j]);
            float2 hi = unp2(acc2[d][2 * j + 1]);
            *(float4*)(op + 4 * j) = make_float4(lo.x, lo.y, hi.x, hi.y);
        }
    }
}

// ---------------------------------------------------------------------------
extern "C" void kernel_launch(void* const* d_in, const int* in_sizes, int n_in,
                              void* d_out, int out_size) {
    const float* inputs     = (const float*)d_in[0];   // [8,256,256,64]
    const float* style      = (const float*)d_in[1];   // [8,512]
    const float* mod_weight = (const float*)d_in[2];   // [512,64]
    const float* mod_bias   = (const float*)d_in[3];   // [64]
    const float* weight     = (const float*)d_in[4];   // [1,64,64,3,3]
    float* out = (float*)d_out;

    k_style<<<8, 512>>>(style, mod_weight, mod_bias);
    k_modw<<<dim3(COUTc, Bq), 64>>>(weight);
    k_conv<<<dim3(Ww / TILE, Hh / TILE, Bq), 256>>>(inputs, out);
}

// round 9
// speedup vs baseline: 4.4400x; 4.3474x over previous
#include <cuda_runtime.h>
#include <cstdint>

#define Bq 8
#define Hh 256
#define Ww 256
#define CINc 64
#define COUTc 64
#define STYLE_INc 512

// ---------------------------------------------------------------------------
// scratch (no allocs allowed)
// ---------------------------------------------------------------------------
__device__ float g_s[Bq * CINc];
// B operand, tf32 bits: [b][h(2)][dy(3)][dx(3)] blocks of [co(64)][ci(32)]
__device__ unsigned g_wB[Bq * 2 * 3 * 3 * 2048];

__device__ __forceinline__ uint32_t to_tf32(float x) {
    uint32_t r;
    asm("cvt.rna.tf32.f32 %0, %1;" : "=r"(r) : "f"(x));
    return r;
}

// ---------------------------------------------------------------------------
// Kernel 1: style modulation (split-K)
// ---------------------------------------------------------------------------
__global__ void k_style(const float* __restrict__ style,
                        const float* __restrict__ mw,
                        const float* __restrict__ mb) {
    const int b  = blockIdx.x;
    const int ci = threadIdx.x & 63;
    const int kp = threadIdx.x >> 6;
    const float scale = 0.04419417382415922f;   // 1/sqrt(512)
    const float* st = style + b * STYLE_INc;
    float acc = 0.f;
    const int k0 = kp * 64;
#pragma unroll 8
    for (int k = k0; k < k0 + 64; ++k)
        acc += st[k] * mw[k * CINc + ci];
    __shared__ float red[512];
    red[threadIdx.x] = acc;
    __syncthreads();
    if (kp == 0) {
        float s = 0.f;
#pragma unroll
        for (int j = 0; j < 8; ++j) s += red[j * 64 + ci];
        g_s[b * CINc + ci] = s * scale + mb[ci];
    }
}

// ---------------------------------------------------------------------------
// Kernel 2: modulate + demodulate, emit tf32 B blocks [co][ci32]
// grid (COUT, B), 64 threads (ci)
// ---------------------------------------------------------------------------
__global__ void k_modw(const float* __restrict__ weight) {
    int co = blockIdx.x;
    int b  = blockIdx.y;
    int ci = threadIdx.x;
    const float cscale = 1.0f / 24.0f;   // 1/sqrt(64*9)
    float sv = g_s[b * CINc + ci];
    const float* wp = weight + (co * CINc + ci) * 9;
    float v[9];
    float ssum = 0.f;
#pragma unroll
    for (int k = 0; k < 9; ++k) {
        v[k] = cscale * wp[k] * sv;
        ssum += v[k] * v[k];
    }
#pragma unroll
    for (int off = 16; off > 0; off >>= 1)
        ssum += __shfl_xor_sync(0xffffffffu, ssum, off);
    __shared__ float red[2];
    if ((ci & 31) == 0) red[ci >> 5] = ssum;
    __syncthreads();
    float demod = rsqrtf(red[0] + red[1] + 1e-8f);
    const int h = ci >> 5;
#pragma unroll
    for (int k = 0; k < 9; ++k) {
        int dy = k / 3, dx = k - 3 * dy;
        unsigned blk = (((b * 2 + h) * 3 + dy) * 3 + dx) * 2048u;
        g_wB[blk + co * 32 + (ci & 31)] = to_tf32(v[k] * demod);
    }
}

// ---------------------------------------------------------------------------
// Kernel 3: implicit-GEMM conv via mma.sync.m16n8k8 tf32.
// CTA = (b, y, x-half): M=128 pixels, N=64 couts, K=576 over 6 stages
// (2 ci-halves x 3 dy), each stage = 3 dx x 4 k8-chunks.
// 8 warps: 4 m-warps (32 px) x 2 n-warps (32 co); warp tile m32 x n32.
// ---------------------------------------------------------------------------
#define APITCH 36                 // words per pixel row (144B, 16B aligned, conflict-free)
__global__ __launch_bounds__(256)
void k_conv(const float* __restrict__ in, float* __restrict__ out) {
    __shared__ __align__(16) unsigned sA[130 * APITCH];       // [px][ci32]
    __shared__ __align__(16) unsigned sB[3 * 64 * APITCH];    // [dx][co][ci32]

    const int x0 = blockIdx.x * 128;
    const int y  = blockIdx.y;
    const int b  = blockIdx.z;
    const int tid = threadIdx.x;
    const int wid = tid >> 5;
    const int lane = tid & 31;
    const int wr = wid >> 1;          // m-warp: pixels wr*32..+31
    const int wc = wid & 1;           // n-warp: couts wc*32..+31
    const int r4 = lane >> 2;         // 0..7
    const int c4 = lane & 3;          // 0..3

    float acc[2][4][4];
#pragma unroll
    for (int mi = 0; mi < 2; ++mi)
#pragma unroll
        for (int ni = 0; ni < 4; ++ni)
#pragma unroll
            for (int j = 0; j < 4; ++j) acc[mi][ni][j] = 0.f;

    const float* inb = in + (size_t)b * Hh * Ww * CINc;

    for (int s = 0; s < 6; ++s) {
        const int h  = s / 3;
        const int dy = s - 3 * h;
        const int y_in = y + dy - 1;
        const bool rowok = (unsigned)y_in < (unsigned)Hh;

        __syncthreads();
        // stage A: 130 px x 32 ci (tf32), pitch 36
        for (int idx = tid; idx < 1040; idx += 256) {
            int p = idx >> 3, f = idx & 7;
            uint4 v = make_uint4(0u, 0u, 0u, 0u);
            int gx = x0 - 1 + p;
            if (rowok && (unsigned)gx < (unsigned)Ww) {
                const float4 t = *(const float4*)(inb +
                    ((size_t)(y_in * Ww + gx) * CINc) + h * 32 + f * 4);
                v.x = to_tf32(t.x); v.y = to_tf32(t.y);
                v.z = to_tf32(t.z); v.w = to_tf32(t.w);
            }
            *(uint4*)(sA + p * APITCH + f * 4) = v;
        }
        // stage B: 3 dx taps x [64 co x 32 ci], pitch 36
        {
            const uint4* src = (const uint4*)(g_wB +
                (size_t)(((b * 2 + h) * 3 + dy) * 3) * 2048);
            for (int idx = tid; idx < 1536; idx += 256) {
                int tap = idx >> 9;          // 0..2
                int rr  = idx & 511;         // co*8 + f
                int co  = rr >> 3, f = rr & 7;
                uint4 v = src[(size_t)tap * 512 + rr];
                *(uint4*)(sB + (tap * 64 + co) * APITCH + f * 4) = v;
            }
        }
        __syncthreads();

#pragma unroll
        for (int dx = 0; dx < 3; ++dx) {
            const unsigned* Ap = sA + (dx + wr * 32) * APITCH;
            const unsigned* Bp = sB + (dx * 64 + wc * 32) * APITCH;
#pragma unroll
            for (int kk = 0; kk < 4; ++kk) {
                const int kc = kk * 8 + c4;
                unsigned a[2][4];
#pragma unroll
                for (int mi = 0; mi < 2; ++mi) {
                    const unsigned* ap = Ap + (mi * 16 + r4) * APITCH + kc;
                    a[mi][0] = ap[0];
                    a[mi][1] = ap[8 * APITCH];
                    a[mi][2] = ap[4];
                    a[mi][3] = ap[8 * APITCH + 4];
                }
                unsigned bfr[4][2];
#pragma unroll
                for (int ni = 0; ni < 4; ++ni) {
                    const unsigned* bp = Bp + (ni * 8 + r4) * APITCH + kc;
                    bfr[ni][0] = bp[0];
                    bfr[ni][1] = bp[4];
                }
#pragma unroll
                for (int mi = 0; mi < 2; ++mi)
#pragma unroll
                    for (int ni = 0; ni < 4; ++ni) {
                        asm volatile(
                            "mma.sync.aligned.m16n8k8.row.col.f32.tf32.tf32.f32 "
                            "{%0,%1,%2,%3}, {%4,%5,%6,%7}, {%8,%9}, {%0,%1,%2,%3};"
                            : "+f"(acc[mi][ni][0]), "+f"(acc[mi][ni][1]),
                              "+f"(acc[mi][ni][2]), "+f"(acc[mi][ni][3])
                            : "r"(a[mi][0]), "r"(a[mi][1]), "r"(a[mi][2]), "r"(a[mi][3]),
                              "r"(bfr[ni][0]), "r"(bfr[ni][1]));
                    }
            }
        }
    }

    // epilogue: c0,c1 -> (row r4, cols 2c4..2c4+1); c2,c3 -> row r4+8
#pragma unroll
    for (int mi = 0; mi < 2; ++mi) {
        const int px0 = x0 + wr * 32 + mi * 16 + r4;
        float* op0 = out + (((size_t)b * Hh + y) * Ww + px0) * COUTc;
        float* op1 = op0 + 8 * (size_t)COUTc;   // row +8
#pragma unroll
        for (int ni = 0; ni < 4; ++ni) {
            const int co = wc * 32 + ni * 8 + 2 * c4;
            *(float2*)(op0 + co) = make_float2(acc[mi][ni][0], acc[mi][ni][1]);
            *(float2*)(op1 + co) = make_float2(acc[mi][ni][2], acc[mi][ni][3]);
        }
    }
}

// ---------------------------------------------------------------------------
extern "C" void kernel_launch(void* const* d_in, const int* in_sizes, int n_in,
                              void* d_out, int out_size) {
    const float* inputs     = (const float*)d_in[0];   // [8,256,256,64]
    const float* style      = (const float*)d_in[1];   // [8,512]
    const float* mod_weight = (const float*)d_in[2];   // [512,64]
    const float* mod_bias   = (const float*)d_in[3];   // [64]
    const float* weight     = (const float*)d_in[4];   // [1,64,64,3,3]
    float* out = (float*)d_out;

    k_style<<<8, 512>>>(style, mod_weight, mod_bias);
    k_modw<<<dim3(COUTc, Bq), 64>>>(weight);
    k_conv<<<dim3(Ww / 128, Hh, Bq), 256>>>(inputs, out);
}

// round 10
// speedup vs baseline: 4.5137x; 1.0166x over previous
#include <cuda_runtime.h>
#include <cstdint>

#define Bq 8
#define Hh 256
#define Ww 256
#define CINc 64
#define COUTc 64
#define STYLE_INc 512

// ---------------------------------------------------------------------------
// scratch (no allocs allowed)
// ---------------------------------------------------------------------------
__device__ float g_s[Bq * CINc];
// B operand, tf32 bits: [b][h(2)][dy(3)][dx(3)] blocks of [co(64)][ci(32)]
__device__ unsigned g_wB[Bq * 2 * 3 * 3 * 2048];

__device__ __forceinline__ uint32_t to_tf32(float x) {
    uint32_t r;
    asm("cvt.rna.tf32.f32 %0, %1;" : "=r"(r) : "f"(x));
    return r;
}

// ---------------------------------------------------------------------------
// Kernel 1: style modulation (split-K)
// ---------------------------------------------------------------------------
__global__ void k_style(const float* __restrict__ style,
                        const float* __restrict__ mw,
                        const float* __restrict__ mb) {
    const int b  = blockIdx.x;
    const int ci = threadIdx.x & 63;
    const int kp = threadIdx.x >> 6;
    const float scale = 0.04419417382415922f;   // 1/sqrt(512)
    const float* st = style + b * STYLE_INc;
    float acc = 0.f;
    const int k0 = kp * 64;
#pragma unroll 8
    for (int k = k0; k < k0 + 64; ++k)
        acc += st[k] * mw[k * CINc + ci];
    __shared__ float red[512];
    red[threadIdx.x] = acc;
    __syncthreads();
    if (kp == 0) {
        float s = 0.f;
#pragma unroll
        for (int j = 0; j < 8; ++j) s += red[j * 64 + ci];
        g_s[b * CINc + ci] = s * scale + mb[ci];
    }
}

// ---------------------------------------------------------------------------
// Kernel 2: modulate + demodulate, emit tf32 B blocks [co][ci32]
// grid (COUT, B), 64 threads (ci)
// ---------------------------------------------------------------------------
__global__ void k_modw(const float* __restrict__ weight) {
    int co = blockIdx.x;
    int b  = blockIdx.y;
    int ci = threadIdx.x;
    const float cscale = 1.0f / 24.0f;   // 1/sqrt(64*9)
    float sv = g_s[b * CINc + ci];
    const float* wp = weight + (co * CINc + ci) * 9;
    float v[9];
    float ssum = 0.f;
#pragma unroll
    for (int k = 0; k < 9; ++k) {
        v[k] = cscale * wp[k] * sv;
        ssum += v[k] * v[k];
    }
#pragma unroll
    for (int off = 16; off > 0; off >>= 1)
        ssum += __shfl_xor_sync(0xffffffffu, ssum, off);
    __shared__ float red[2];
    if ((ci & 31) == 0) red[ci >> 5] = ssum;
    __syncthreads();
    float demod = rsqrtf(red[0] + red[1] + 1e-8f);
    const int h = ci >> 5;
#pragma unroll
    for (int k = 0; k < 9; ++k) {
        int dy = k / 3, dx = k - 3 * dy;
        unsigned blk = (((b * 2 + h) * 3 + dy) * 3 + dx) * 2048u;
        g_wB[blk + co * 32 + (ci & 31)] = to_tf32(v[k] * demod);
    }
}

// ---------------------------------------------------------------------------
// Kernel 3: implicit-GEMM conv, mma.sync.m16n8k8 tf32.
// CTA = (x-half, y-pair, b): M=256 (2 rows x 128 px), N=64, K=576.
// 6 stages (2 ci-halves x 3 dy); stage stages 2 input rows + 3 dx weight taps.
// 8 warps = 4 m-warps (64 px) x 2 n-warps (32 co); warp tile m64 x n32.
// Register-prefetch: LDG for stage s+1 issued before mma of stage s.
// ---------------------------------------------------------------------------
#define APITCH 36                 // words per pixel/co row (144B, conflict-free)
#define A_WORDS (2 * 130 * APITCH)   // 9360
#define B_WORDS (3 * 64 * APITCH)    // 6912
#define SMEM_BYTES ((A_WORDS + B_WORDS) * 4)   // 65088

__global__ __launch_bounds__(256)
void k_conv(const float* __restrict__ in, float* __restrict__ out) {
    extern __shared__ __align__(16) unsigned dynsm[];
    unsigned* sA = dynsm;              // [r(2)][px(130)][ci32] pitch 36
    unsigned* sB = dynsm + A_WORDS;    // [dx(3)][co(64)][ci32] pitch 36

    const int x0 = blockIdx.x * 128;
    const int y0 = blockIdx.y * 2;
    const int b  = blockIdx.z;
    const int tid = threadIdx.x;
    const int wid = tid >> 5;
    const int lane = tid & 31;
    const int rr   = wid >> 2;            // output row within pair (0/1)
    const int xoff = ((wid >> 1) & 1) * 64;  // x-quarter base
    const int wc   = wid & 1;             // n-warp: couts wc*32..+31
    const int r4 = lane >> 2;             // 0..7
    const int c4 = lane & 3;              // 0..3

    float acc[4][4][4];
#pragma unroll
    for (int mi = 0; mi < 4; ++mi)
#pragma unroll
        for (int ni = 0; ni < 4; ++ni)
#pragma unroll
            for (int j = 0; j < 4; ++j) acc[mi][ni][j] = 0.f;

    const float* inb = in + (size_t)b * Hh * Ww * CINc;

    float4 rAf[9];
    uint4  rB[6];

    // prefetch LDG for stage (h,dy): A = 2 rows x 130 px x 8 f; B = 1536 uint4
#define LDG_STAGE(hh, dyy)                                                     \
    {                                                                          \
        _Pragma("unroll")                                                      \
        for (int k = 0; k < 9; ++k) {                                          \
            int idx = tid + k * 256;                                           \
            float4 v = make_float4(0.f, 0.f, 0.f, 0.f);                        \
            if (idx < 2080) {                                                  \
                int r   = (idx >= 1040) ? 1 : 0;                               \
                int rem = idx - r * 1040;                                      \
                int p   = rem >> 3, f = rem & 7;                               \
                int in_r = y0 + (dyy)-1 + r;                                   \
                int gx   = x0 - 1 + p;                                         \
                if ((unsigned)in_r < (unsigned)Hh && (unsigned)gx < (unsigned)Ww) \
                    v = *(const float4*)(inb +                                 \
                        ((size_t)(in_r * Ww + gx) * CINc) + (hh)*32 + f * 4);  \
            }                                                                  \
            rAf[k] = v;                                                        \
        }                                                                      \
        const uint4* bsrc = (const uint4*)(g_wB +                              \
            (size_t)(((b * 2 + (hh)) * 3 + (dyy)) * 3) * 2048);                \
        _Pragma("unroll")                                                      \
        for (int j = 0; j < 6; ++j) rB[j] = bsrc[tid + j * 256];               \
    }

    LDG_STAGE(0, 0);   // prologue: stage 0

    for (int s = 0; s < 6; ++s) {
        // ---- STS stage s from registers (cvt A here, B pre-converted) ----
#pragma unroll
        for (int k = 0; k < 9; ++k) {
            int idx = tid + k * 256;
            if (idx < 2080) {
                int r   = (idx >= 1040) ? 1 : 0;
                int rem = idx - r * 1040;
                int p   = rem >> 3, f = rem & 7;
                uint4 v;
                v.x = to_tf32(rAf[k].x); v.y = to_tf32(rAf[k].y);
                v.z = to_tf32(rAf[k].z); v.w = to_tf32(rAf[k].w);
                *(uint4*)(sA + (r * 130 + p) * APITCH + f * 4) = v;
            }
        }
#pragma unroll
        for (int j = 0; j < 6; ++j) {
            int i = tid + j * 256;
            int tap = i >> 9;
            int rw  = i & 511;          // co*8 + f
            int co  = rw >> 3, f = rw & 7;
            *(uint4*)(sB + (tap * 64 + co) * APITCH + f * 4) = rB[j];
        }
        __syncthreads();

        // ---- prefetch stage s+1 (overlaps with mma below) ----
        if (s < 5) {
            int s1 = s + 1;
            int h1 = s1 / 3, dy1 = s1 - 3 * h1;
            LDG_STAGE(h1, dy1);
        }

        // ---- mma over 3 dx taps x 4 k8-chunks ----
#pragma unroll
        for (int dx = 0; dx < 3; ++dx) {
            const unsigned* Ap = sA + (rr * 130 + xoff + dx) * APITCH;
            const unsigned* Bp = sB + (dx * 64 + wc * 32) * APITCH;
#pragma unroll
            for (int kk = 0; kk < 4; ++kk) {
                const int kc = kk * 8 + c4;
                unsigned a[4][4];
#pragma unroll
                for (int mi = 0; mi < 4; ++mi) {
                    const unsigned* ap = Ap + (mi * 16 + r4) * APITCH + kc;
                    a[mi][0] = ap[0];
                    a[mi][1] = ap[8 * APITCH];
                    a[mi][2] = ap[4];
                    a[mi][3] = ap[8 * APITCH + 4];
                }
                unsigned bfr[4][2];
#pragma unroll
                for (int ni = 0; ni < 4; ++ni) {
                    const unsigned* bp = Bp + (ni * 8 + r4) * APITCH + kc;
                    bfr[ni][0] = bp[0];
                    bfr[ni][1] = bp[4];
                }
#pragma unroll
                for (int mi = 0; mi < 4; ++mi)
#pragma unroll
                    for (int ni = 0; ni < 4; ++ni) {
                        asm volatile(
                            "mma.sync.aligned.m16n8k8.row.col.f32.tf32.tf32.f32 "
                            "{%0,%1,%2,%3}, {%4,%5,%6,%7}, {%8,%9}, {%0,%1,%2,%3};"
                            : "+f"(acc[mi][ni][0]), "+f"(acc[mi][ni][1]),
                              "+f"(acc[mi][ni][2]), "+f"(acc[mi][ni][3])
                            : "r"(a[mi][0]), "r"(a[mi][1]), "r"(a[mi][2]), "r"(a[mi][3]),
                              "r"(bfr[ni][0]), "r"(bfr[ni][1]));
                    }
            }
        }
        __syncthreads();
    }

    // epilogue: c0,c1 -> (px r4, cols 2c4..2c4+1); c2,c3 -> px r4+8
    const int y = y0 + rr;
#pragma unroll
    for (int mi = 0; mi < 4; ++mi) {
        const int px0 = x0 + xoff + mi * 16 + r4;
        float* op0 = out + (((size_t)b * Hh + y) * Ww + px0) * COUTc;
        float* op1 = op0 + 8 * (size_t)COUTc;   // pixel +8
#pragma unroll
        for (int ni = 0; ni < 4; ++ni) {
            const int co = wc * 32 + ni * 8 + 2 * c4;
            *(float2*)(op0 + co) = make_float2(acc[mi][ni][0], acc[mi][ni][1]);
            *(float2*)(op1 + co) = make_float2(acc[mi][ni][2], acc[mi][ni][3]);
        }
    }
}

// ---------------------------------------------------------------------------
extern "C" void kernel_launch(void* const* d_in, const int* in_sizes, int n_in,
                              void* d_out, int out_size) {
    const float* inputs     = (const float*)d_in[0];   // [8,256,256,64]
    const float* style      = (const float*)d_in[1];   // [8,512]
    const float* mod_weight = (const float*)d_in[2];   // [512,64]
    const float* mod_bias   = (const float*)d_in[3];   // [64]
    const float* weight     = (const float*)d_in[4];   // [1,64,64,3,3]
    float* out = (float*)d_out;

    cudaFuncSetAttribute(k_conv, cudaFuncAttributeMaxDynamicSharedMemorySize,
                         SMEM_BYTES);

    k_style<<<8, 512>>>(style, mod_weight, mod_bias);
    k_modw<<<dim3(COUTc, Bq), 64>>>(weight);
    k_conv<<<dim3(Ww / 128, Hh / 2, Bq), 256, SMEM_BYTES>>>(inputs, out);
}

// round 15
// speedup vs baseline: 7.0756x; 1.5676x over previous
#include <cuda_runtime.h>
#include <cuda_fp16.h>
#include <cstdint>

#define Bq 8
#define Hh 256
#define Ww 256
#define CINc 64
#define COUTc 64
#define STYLE_INc 512

// ---------------------------------------------------------------------------
// scratch (no allocs allowed)
// ---------------------------------------------------------------------------
__device__ float g_s[Bq * CINc];
// B operand, fp16: [b][h(2)][dy(3)][dx(3)] blocks of [co(64)][ci(32)] halves
__device__ __half g_wBh[Bq * 2 * 3 * 3 * 2048];

// ---------------------------------------------------------------------------
// Kernel 1: style modulation (split-K)
// ---------------------------------------------------------------------------
__global__ void k_style(const float* __restrict__ style,
                        const float* __restrict__ mw,
                        const float* __restrict__ mb) {
    const int b  = blockIdx.x;
    const int ci = threadIdx.x & 63;
    const int kp = threadIdx.x >> 6;
    const float scale = 0.04419417382415922f;   // 1/sqrt(512)
    const float* st = style + b * STYLE_INc;
    float acc = 0.f;
    const int k0 = kp * 64;
#pragma unroll 8
    for (int k = k0; k < k0 + 64; ++k)
        acc += st[k] * mw[k * CINc + ci];
    __shared__ float red[512];
    red[threadIdx.x] = acc;
    __syncthreads();
    if (kp == 0) {
        float s = 0.f;
#pragma unroll
        for (int j = 0; j < 8; ++j) s += red[j * 64 + ci];
        g_s[b * CINc + ci] = s * scale + mb[ci];
    }
}

// ---------------------------------------------------------------------------
// Kernel 2: modulate + demodulate, emit fp16 B blocks [co][ci32]
// grid (COUT, B), 64 threads (ci)
// ---------------------------------------------------------------------------
__global__ void k_modw(const float* __restrict__ weight) {
    int co = blockIdx.x;
    int b  = blockIdx.y;
    int ci = threadIdx.x;
    const float cscale = 1.0f / 24.0f;   // 1/sqrt(64*9)
    float sv = g_s[b * CINc + ci];
    const float* wp = weight + (co * CINc + ci) * 9;
    float v[9];
    float ssum = 0.f;
#pragma unroll
    for (int k = 0; k < 9; ++k) {
        v[k] = cscale * wp[k] * sv;
        ssum += v[k] * v[k];
    }
#pragma unroll
    for (int off = 16; off > 0; off >>= 1)
        ssum += __shfl_xor_sync(0xffffffffu, ssum, off);
    __shared__ float red[2];
    if ((ci & 31) == 0) red[ci >> 5] = ssum;
    __syncthreads();
    float demod = rsqrtf(red[0] + red[1] + 1e-8f);
    const int h = ci >> 5;
#pragma unroll
    for (int k = 0; k < 9; ++k) {
        int dy = k / 3, dx = k - 3 * dy;
        unsigned blk = (((b * 2 + h) * 3 + dy) * 3 + dx) * 2048u;
        g_wBh[blk + co * 32 + (ci & 31)] = __float2half_rn(v[k] * demod);
    }
}

// ---------------------------------------------------------------------------
// Kernel 3: implicit-GEMM conv, mma.sync.m16n8k16 fp16 (f32 accum).
// CTA = (x-half, y-pair, b): M=256 (2 rows x 128 px), N=64, K=576.
// 6 stages (2 ci-halves x 3 dy); each stage = 3 dx taps x 2 k16-chunks.
// 8 warps = (row, x-quarter, n-half); warp tile m64 x n32.
// Register-prefetch of stage s+1 LDG before mma of stage s.
// ---------------------------------------------------------------------------
#define APITCH 20                 // u32 words per pixel/co row (80B, conflict-free)
#define A_WORDS (2 * 130 * APITCH)   // 5200
#define B_WORDS (3 * 64 * APITCH)    // 3840

__global__ __launch_bounds__(256)
void k_conv(const float* __restrict__ in, float* __restrict__ out) {
    __shared__ __align__(16) unsigned sA[A_WORDS];   // [r(2)][px(130)][ci16x2] pitch 20
    __shared__ __align__(16) unsigned sB[B_WORDS];   // [dx(3)][co(64)][ci16x2] pitch 20

    const int x0 = blockIdx.x * 128;
    const int y0 = blockIdx.y * 2;
    const int b  = blockIdx.z;
    const int tid = threadIdx.x;
    const int wid = tid >> 5;
    const int lane = tid & 31;
    const int rr   = wid >> 2;               // output row within pair (0/1)
    const int xoff = ((wid >> 1) & 1) * 64;  // x-quarter base
    const int wc   = wid & 1;                // n-warp: couts wc*32..+31
    const int r4 = lane >> 2;                // 0..7
    const int c4 = lane & 3;                 // 0..3

    float acc[4][4][4];
#pragma unroll
    for (int mi = 0; mi < 4; ++mi)
#pragma unroll
        for (int ni = 0; ni < 4; ++ni)
#pragma unroll
            for (int j = 0; j < 4; ++j) acc[mi][ni][j] = 0.f;

    const float* inb = in + (size_t)b * Hh * Ww * CINc;

    float4 rAf[9];
    uint4  rB[3];

    // prefetch LDG for stage (h,dy): A = 2 rows x 130 px x 8 f (fp32);
    // B = 3 taps x 64 co x 32 ci fp16 = 768 uint4
#define LDG_STAGE(hh, dyy)                                                     \
    {                                                                          \
        _Pragma("unroll")                                                      \
        for (int k = 0; k < 9; ++k) {                                          \
            int idx = tid + k * 256;                                           \
            float4 v = make_float4(0.f, 0.f, 0.f, 0.f);                        \
            if (idx < 2080) {                                                  \
                int r   = (idx >= 1040) ? 1 : 0;                               \
                int rem = idx - r * 1040;                                      \
                int p   = rem >> 3, f = rem & 7;                               \
                int in_r = y0 + (dyy)-1 + r;                                   \
                int gx   = x0 - 1 + p;                                         \
                if ((unsigned)in_r < (unsigned)Hh && (unsigned)gx < (unsigned)Ww) \
                    v = *(const float4*)(inb +                                 \
                        ((size_t)(in_r * Ww + gx) * CINc) + (hh)*32 + f * 4);  \
            }                                                                  \
            rAf[k] = v;                                                        \
        }                                                                      \
        const uint4* bsrc = (const uint4*)(g_wBh +                             \
            (size_t)(((b * 2 + (hh)) * 3 + (dyy)) * 3) * 2048);                \
        _Pragma("unroll")                                                      \
        for (int j = 0; j < 3; ++j) rB[j] = bsrc[tid + j * 256];               \
    }

    LDG_STAGE(0, 0);   // prologue: stage 0

    for (int s = 0; s < 6; ++s) {
        // ---- STS stage s from registers (cvt fp32->fp16 here) ----
#pragma unroll
        for (int k = 0; k < 9; ++k) {
            int idx = tid + k * 256;
            if (idx < 2080) {
                int r   = (idx >= 1040) ? 1 : 0;
                int rem = idx - r * 1040;
                int p   = rem >> 3, f = rem & 7;
                __half2 h0 = __floats2half2_rn(rAf[k].x, rAf[k].y);
                __half2 h1 = __floats2half2_rn(rAf[k].z, rAf[k].w);
                uint2 w;
                w.x = *(unsigned*)&h0;
                w.y = *(unsigned*)&h1;
                *(uint2*)(sA + (r * 130 + p) * APITCH + f * 2) = w;
            }
        }
#pragma unroll
        for (int j = 0; j < 3; ++j) {
            int i = tid + j * 256;          // < 768
            int tap = i >> 8;               // 0..2 (256 uint4 per tap)
            int rm  = i & 255;              // co*4 + f
            int co  = rm >> 2, f = rm & 3;
            *(uint4*)(sB + (tap * 64 + co) * APITCH + f * 4) = rB[j];
        }
        __syncthreads();

        // ---- prefetch stage s+1 (overlaps with mma below) ----
        if (s < 5) {
            int s1 = s + 1;
            int h1 = s1 / 3, dy1 = s1 - 3 * h1;
            LDG_STAGE(h1, dy1);
        }

        // ---- mma over 3 dx taps x 2 k16-chunks ----
#pragma unroll
        for (int dx = 0; dx < 3; ++dx) {
            const unsigned* Ap = sA + (rr * 130 + xoff + dx) * APITCH;
            const unsigned* Bp = sB + (dx * 64 + wc * 32) * APITCH;
#pragma unroll
            for (int kk = 0; kk < 2; ++kk) {
                const int kc = kk * 8 + c4;
                unsigned a[4][4];
#pragma unroll
                for (int mi = 0; mi < 4; ++mi) {
                    const unsigned* ap = Ap + (mi * 16 + r4) * APITCH + kc;
                    a[mi][0] = ap[0];                    // (r4,   k 2c4)
                    a[mi][1] = ap[8 * APITCH];           // (r4+8, k 2c4)
                    a[mi][2] = ap[4];                    // (r4,   k 2c4+8)
                    a[mi][3] = ap[8 * APITCH + 4];       // (r4+8, k 2c4+8)
                }
                unsigned bfr[4][2];
#pragma unroll
                for (int ni = 0; ni < 4; ++ni) {
                    const unsigned* bp = Bp + (ni * 8 + r4) * APITCH + kc;
                    bfr[ni][0] = bp[0];                  // (k 2c4,   n r4)
                    bfr[ni][1] = bp[4];                  // (k 2c4+8, n r4)
                }
#pragma unroll
                for (int mi = 0; mi < 4; ++mi)
#pragma unroll
                    for (int ni = 0; ni < 4; ++ni) {
                        asm volatile(
                            "mma.sync.aligned.m16n8k16.row.col.f32.f16.f16.f32 "
                            "{%0,%1,%2,%3}, {%4,%5,%6,%7}, {%8,%9}, {%0,%1,%2,%3};"
                            : "+f"(acc[mi][ni][0]), "+f"(acc[mi][ni][1]),
                              "+f"(acc[mi][ni][2]), "+f"(acc[mi][ni][3])
                            : "r"(a[mi][0]), "r"(a[mi][1]), "r"(a[mi][2]), "r"(a[mi][3]),
                              "r"(bfr[ni][0]), "r"(bfr[ni][1]));
                    }
            }
        }
        __syncthreads();
    }

    // epilogue: c0,c1 -> (px r4, cols 2c4..2c4+1); c2,c3 -> px r4+8
    const int y = y0 + rr;
#pragma unroll
    for (int mi = 0; mi < 4; ++mi) {
        const int px0 = x0 + xoff + mi * 16 + r4;
        float* op0 = out + (((size_t)b * Hh + y) * Ww + px0) * COUTc;
        float* op1 = op0 + 8 * (size_t)COUTc;   // pixel +8
#pragma unroll
        for (int ni = 0; ni < 4; ++ni) {
            const int co = wc * 32 + ni * 8 + 2 * c4;
            *(float2*)(op0 + co) = make_float2(acc[mi][ni][0], acc[mi][ni][1]);
            *(float2*)(op1 + co) = make_float2(acc[mi][ni][2], acc[mi][ni][3]);
        }
    }
}

// ---------------------------------------------------------------------------
extern "C" void kernel_launch(void* const* d_in, const int* in_sizes, int n_in,
                              void* d_out, int out_size) {
    const float* inputs     = (const float*)d_in[0];   // [8,256,256,64]
    const float* style      = (const float*)d_in[1];   // [8,512]
    const float* mod_weight = (const float*)d_in[2];   // [512,64]
    const float* mod_bias   = (const float*)d_in[3];   // [64]
    const float* weight     = (const float*)d_in[4];   // [1,64,64,3,3]
    float* out = (float*)d_out;

    k_style<<<8, 512>>>(style, mod_weight, mod_bias);
    k_modw<<<dim3(COUTc, Bq), 64>>>(weight);
    k_conv<<<dim3(Ww / 128, Hh / 2, Bq), 256>>>(inputs, out);
}